// round 14
// baseline (speedup 1.0000x reference)
#include <cuda_runtime.h>
#include <cuda_bf16.h>
#include <cstddef>

// hungarian_matcher cost kernel
// out[b, q, j] = 5 * sum_d |pred_boxes[b,q,d] - target_boxes[b*64+j, d]|
//              - softmax(pred_logits[b,q,:])[target_ids[b*64+j]]
//
// R14 = R13 (warp-autonomous, NO __syncthreads — proven: issue 36->51%,
// dur 7.232) + R10's vectorized smem reads (proven instruction cut):
// warp-private tiles padded to 12-float rows so the per-thread target box
// is 3 LDS.128 (48B lane stride -> conflict-free) and each pred row is 3
// broadcast LDS.128 instead of 11 scalar LDS. Staging dst = s + s/11
// (constant-div mul-shift, ~3 IMADs per element).
//
// Block (32,8)=256, grid (45,16)=720. Warp w = (qy=w>>1, jhalf=w&1) owns
// queries qw..qw+5 and targets jhalf*32..+32; softmax computed in-lane
// (lane 4k+c -> -softmax(q_k)[c]) and distributed via __shfl_sync.

namespace {

constexpr int BOX  = 11;
constexpr int BOXP = 12;         // padded row (48B, float4-aligned)
constexpr int NC   = 4;
constexpr int PER  = 64;
constexpr int QPT  = 5;          // queries per warp
constexpr int QT   = 20;         // queries per CTA (900 = 45*20)
constexpr int NW   = 8;          // warps per CTA
constexpr int NT   = 32 * NW;    // 256 threads

constexpr int TWE  = 32 * BOX;   // 352 source target floats per warp
constexpr int TWP  = 32 * BOXP;  // 384 padded slots
constexpr int PWE  = QPT * BOX;  // 55 source pred floats per warp
constexpr int PWP  = QPT * BOXP; // 60 padded slots

__global__ __launch_bounds__(NT)
void matcher_kernel(const float* __restrict__ logits,
                    const float* __restrict__ boxes,
                    const float* __restrict__ tboxes,
                    const int*   __restrict__ tids,
                    float* __restrict__ out,
                    int nq)
{
    const int b    = blockIdx.y;
    const int q0   = blockIdx.x * QT;
    const int lane = threadIdx.x;        // 0..31
    const int w    = threadIdx.y;        // 0..7
    const int qy   = w >> 1;             // 0..3
    const int jh   = w & 1;              // 0..1
    const int qw   = q0 + qy * QPT;      // first query of this warp
    const int j    = jh * 32 + lane;     // this lane's target

    __shared__ float s_t[NW][TWP];       // warp-private padded target tiles
    __shared__ float s_p[NW][PWP];       // warp-private padded pred tiles

    // --- Stage this warp's 32 target rows (coalesced LDG, padded STS) ---
    {
        const float* src = tboxes + ((size_t)b * PER + jh * 32) * BOX;
#pragma unroll
        for (int i = 0; i < BOX; i++) {
            const int s = lane + 32 * i;         // 0..351
            s_t[w][s + s / BOX] = src[s];        // row*12+col = s + s/11
        }
    }

    // --- Stage this warp's 5 pred rows (55 floats, 2 rounds, padded) ---
    {
        const float* src = boxes + ((size_t)b * nq + qw) * BOX;
#pragma unroll
        for (int i = 0; i < 2; i++) {
            const int s = lane + 32 * i;
            if (s < PWE) s_p[w][s + s / BOX] = src[s];
        }
    }

    // --- Softmax: lane 4k+c (k<5, c<4) computes -softmax(q_k)[c] ---
    float np_lane = 0.0f;
    if (lane < QPT * NC) {
        const int k = lane >> 2, c = lane & 3;
        const float4 lg = *(const float4*)(logits + ((size_t)b * nq + qw + k) * NC);
        const float m = fmaxf(fmaxf(lg.x, lg.y), fmaxf(lg.z, lg.w));
        const float e0 = __expf(lg.x - m), e1 = __expf(lg.y - m);
        const float e2 = __expf(lg.z - m), e3 = __expf(lg.w - m);
        const float inv = __frcp_rn(e0 + e1 + e2 + e3);
        const float ec = (c == 0) ? e0 : (c == 1) ? e1 : (c == 2) ? e2 : e3;
        np_lane = -ec * inv;
    }

    // Class id for this lane's target (coalesced)
    const int cls = tids[b * PER + j];

    __syncwarp();

    // --- Gather the 5 negprob values this lane needs via shuffle ---
    float np[QPT];
#pragma unroll
    for (int k = 0; k < QPT; k++)
        np[k] = __shfl_sync(0xffffffffu, np_lane, (k << 2) | cls);

    // --- Target box -> registers: 3 LDS.128 (48B stride, conflict-free) ---
    float tb[BOXP];
    {
        const float4* tr = (const float4*)(s_t[w] + lane * BOXP);
#pragma unroll
        for (int v = 0; v < 3; v++) ((float4*)tb)[v] = tr[v];
    }

    // --- 5 query rows; 3 broadcast LDS.128 per pred row ---
    float* orow = out + ((size_t)b * nq + qw) * PER + j;
#pragma unroll
    for (int k = 0; k < QPT; k++) {
        float pbf[BOXP];
        {
            const float4* pr = (const float4*)(s_p[w] + k * BOXP);
#pragma unroll
            for (int v = 0; v < 3; v++) ((float4*)pbf)[v] = pr[v];
        }

        float sa = 0.0f, sb = 0.0f;
#pragma unroll
        for (int d = 0; d < BOX; d += 2) {
            sa += fabsf(pbf[d] - tb[d]);
            if (d + 1 < BOX) sb += fabsf(pbf[d + 1] - tb[d + 1]);
        }
        orow[(size_t)k * PER] = fmaf(5.0f, sa + sb, np[k]);
    }
}

} // namespace

extern "C" void kernel_launch(void* const* d_in, const int* in_sizes, int n_in,
                              void* d_out, int out_size)
{
    const float* logits = (const float*)d_in[0];
    const float* boxes  = (const float*)d_in[1];
    const float* tboxes = (const float*)d_in[2];
    const int*   tids   = (const int*)d_in[3];
    float* out = (float*)d_out;

    const int n_total = in_sizes[3];                 // 1024
    const int box_dim = in_sizes[2] / n_total;       // 11
    const int bsnq    = in_sizes[1] / box_dim;       // 14400
    const int per     = out_size / bsnq;             // 64
    const int bs      = n_total / per;               // 16
    const int nq      = bsnq / bs;                   // 900

    (void)n_in; (void)box_dim; (void)per;

    dim3 block(32, NW);
    dim3 grid(nq / QT, bs);                          // (45, 16) = 720
    matcher_kernel<<<grid, block>>>(logits, boxes, tboxes, tids, out, nq);
}

// round 15
// speedup vs baseline: 1.1372x; 1.1372x over previous
#include <cuda_runtime.h>
#include <cuda_bf16.h>
#include <cstddef>

// hungarian_matcher cost kernel
// out[b, q, j] = 5 * sum_d |pred_boxes[b,q,d] - target_boxes[b*64+j, d]|
//              - softmax(pred_logits[b,q,:])[target_ids[b*64+j]]
//
// R15 = R13 (warp-autonomous, no __syncthreads; best: dur 7.232, issue
// 51%) + ONE change: the warp-private pred tile is padded to 12-float
// rows (padding math on only the 2 staging elements per thread) so each
// pred row in the hot loop is 3 broadcast LDS.128 instead of 11 scalar
// LDS. Target tile stays R13-scalar (immediate-offset LDS, no padding
// math) — R14 showed vectorizing IT costs more in staging IMADs than the
// LDS it saves.
//
// Block (32,8)=256, grid (45,16)=720. Warp w = (qy=w>>1, jhalf=w&1) owns
// queries qw..qw+5 and targets jhalf*32..+32; softmax computed in-lane
// (lane 4k+c -> -softmax(q_k)[c]) and distributed via __shfl_sync.

namespace {

constexpr int BOX  = 11;
constexpr int BOXP = 12;         // padded pred row (48B, float4-aligned)
constexpr int NC   = 4;
constexpr int PER  = 64;
constexpr int QPT  = 5;          // queries per warp
constexpr int QT   = 20;         // queries per CTA (900 = 45*20)
constexpr int NW   = 8;          // warps per CTA
constexpr int NT   = 32 * NW;    // 256 threads

constexpr int TW   = 32 * BOX;   // 352: target floats per warp (unpadded)
constexpr int PWE  = QPT * BOX;  // 55 source pred floats per warp
constexpr int PWP  = QPT * BOXP; // 60 padded slots

__global__ __launch_bounds__(NT)
void matcher_kernel(const float* __restrict__ logits,
                    const float* __restrict__ boxes,
                    const float* __restrict__ tboxes,
                    const int*   __restrict__ tids,
                    float* __restrict__ out,
                    int nq)
{
    const int b    = blockIdx.y;
    const int q0   = blockIdx.x * QT;
    const int lane = threadIdx.x;        // 0..31
    const int w    = threadIdx.y;        // 0..7
    const int qy   = w >> 1;             // 0..3
    const int jh   = w & 1;              // 0..1
    const int qw   = q0 + qy * QPT;      // first query of this warp
    const int j    = jh * 32 + lane;     // this lane's target

    __shared__ float s_t[NW][TW];        // warp-private target tiles (unpadded)
    __shared__ float s_p[NW][PWP];       // warp-private padded pred tiles

    // --- Stage this warp's 32 target rows: 11 coalesced LDG + STS ---
    {
        const float* src = tboxes + ((size_t)b * PER + jh * 32) * BOX;
#pragma unroll
        for (int i = 0; i < BOX; i++) {
            const int s = lane + 32 * i;
            s_t[w][s] = src[s];
        }
    }

    // --- Stage this warp's 5 pred rows (55 floats, padded dst, 2 rounds) ---
    {
        const float* src = boxes + ((size_t)b * nq + qw) * BOX;
#pragma unroll
        for (int i = 0; i < 2; i++) {
            const int s = lane + 32 * i;
            if (s < PWE) s_p[w][s + s / BOX] = src[s];  // row*12+col
        }
    }

    // --- Softmax: lane 4k+c (k<5, c<4) computes -softmax(q_k)[c] ---
    float np_lane = 0.0f;
    if (lane < QPT * NC) {
        const int k = lane >> 2, c = lane & 3;
        const float4 lg = *(const float4*)(logits + ((size_t)b * nq + qw + k) * NC);
        const float m = fmaxf(fmaxf(lg.x, lg.y), fmaxf(lg.z, lg.w));
        const float e0 = __expf(lg.x - m), e1 = __expf(lg.y - m);
        const float e2 = __expf(lg.z - m), e3 = __expf(lg.w - m);
        const float inv = __frcp_rn(e0 + e1 + e2 + e3);
        const float ec = (c == 0) ? e0 : (c == 1) ? e1 : (c == 2) ? e2 : e3;
        np_lane = -ec * inv;
    }

    // Class id for this lane's target (coalesced)
    const int cls = tids[b * PER + j];

    __syncwarp();

    // --- Gather the 5 negprob values this lane needs via shuffle ---
    float np[QPT];
#pragma unroll
    for (int k = 0; k < QPT; k++)
        np[k] = __shfl_sync(0xffffffffu, np_lane, (k << 2) | cls);

    // --- Target box -> registers: 11 scalar LDS, stride 11, conflict-free,
    //     immediate offsets off one base (no addressing math) ---
    float tb[BOX];
#pragma unroll
    for (int d = 0; d < BOX; d++) tb[d] = s_t[w][lane * BOX + d];

    // --- 5 query rows; 3 broadcast LDS.128 per pred row ---
    float* orow = out + ((size_t)b * nq + qw) * PER + j;
#pragma unroll
    for (int k = 0; k < QPT; k++) {
        float pbf[BOXP];
        {
            const float4* pr = (const float4*)(s_p[w] + k * BOXP);
#pragma unroll
            for (int v = 0; v < 3; v++) ((float4*)pbf)[v] = pr[v];
        }

        float sa = 0.0f, sb = 0.0f;
#pragma unroll
        for (int d = 0; d < BOX; d += 2) {
            sa += fabsf(pbf[d] - tb[d]);
            if (d + 1 < BOX) sb += fabsf(pbf[d + 1] - tb[d + 1]);
        }
        orow[(size_t)k * PER] = fmaf(5.0f, sa + sb, np[k]);
    }
}

} // namespace

extern "C" void kernel_launch(void* const* d_in, const int* in_sizes, int n_in,
                              void* d_out, int out_size)
{
    const float* logits = (const float*)d_in[0];
    const float* boxes  = (const float*)d_in[1];
    const float* tboxes = (const float*)d_in[2];
    const int*   tids   = (const int*)d_in[3];
    float* out = (float*)d_out;

    const int n_total = in_sizes[3];                 // 1024
    const int box_dim = in_sizes[2] / n_total;       // 11
    const int bsnq    = in_sizes[1] / box_dim;       // 14400
    const int per     = out_size / bsnq;             // 64
    const int bs      = n_total / per;               // 16
    const int nq      = bsnq / bs;                   // 900

    (void)n_in; (void)box_dim; (void)per;

    dim3 block(32, NW);
    dim3 grid(nq / QT, bs);                          // (45, 16) = 720
    matcher_kernel<<<grid, block>>>(logits, boxes, tboxes, tids, out, nq);
}